// round 11
// baseline (speedup 1.0000x reference)
#include <cuda_runtime.h>
#include <cuda_bf16.h>
#include <cstdint>

// ============================================================================
// ModelR: x[8192,1024] -> (Linear+LeakyReLU) x4 -> Linear -> tri-scatter
// Round 11: occupancy experiment — 512 threads / 16 warps per CTA
// (4 warps/SMSP instead of 2) on the same BM=128,BN=256,BK=64 2-stage tile.
// Warp tile 64x32 (warp grid 2 x 8). Tests whether the ~650 MAC/cyc/SM
// ceiling is latency exposure (more warps fix it) or pipe rate (neutral).
// Also: memset fused into scatter (mirror zeros), saving a 134MB pass.
//   D = Ah*Bh + Ah*Bl + Al*Bh  (bf16 hi/lo split, fp32 accum, err ~2^-16)
// ============================================================================

#define BATCH 8192
#define DIN   1024
#define HID   2048
#define LOUT  2080
#define CPV   64

#define PITCH   144         // 128B payload (64 bf16) + 16B pad
#define OFF_AH  0
#define OFF_AL  18432       // 128 rows * 144B
#define OFF_BH  36864
#define OFF_BL  73728       // OFF_BH + 256 rows * 144B
#define STAGE   110592
#define NSTAGE  2
#define SMEMSZ  (NSTAGE * STAGE)   // 221184 B
#define NTHREADS 512

// ------------------------- device scratch (no allocs) -----------------------
__device__ __nv_bfloat16 g_Ah0[(size_t)BATCH * HID];
__device__ __nv_bfloat16 g_Al0[(size_t)BATCH * HID];
__device__ __nv_bfloat16 g_Ah1[(size_t)BATCH * HID];
__device__ __nv_bfloat16 g_Al1[(size_t)BATCH * HID];
__device__ __nv_bfloat16 g_W1h[(size_t)HID * DIN];
__device__ __nv_bfloat16 g_W1l[(size_t)HID * DIN];
__device__ __nv_bfloat16 g_W2h[(size_t)HID * HID];
__device__ __nv_bfloat16 g_W2l[(size_t)HID * HID];
__device__ __nv_bfloat16 g_W21h[(size_t)HID * HID];
__device__ __nv_bfloat16 g_W21l[(size_t)HID * HID];
__device__ __nv_bfloat16 g_W22h[(size_t)HID * HID];
__device__ __nv_bfloat16 g_W22l[(size_t)HID * HID];
__device__ __nv_bfloat16 g_W3h[(size_t)LOUT * HID];
__device__ __nv_bfloat16 g_W3l[(size_t)LOUT * HID];
__device__ float         g_Y[(size_t)BATCH * LOUT];

// ------------------------------ PTX helpers ---------------------------------
__device__ __forceinline__ uint32_t smem_u32(const void* p) {
    uint32_t a;
    asm("{ .reg .u64 t; cvta.to.shared.u64 t, %1; cvt.u32.u64 %0, t; }"
        : "=r"(a) : "l"(p));
    return a;
}
__device__ __forceinline__ void cp16(uint32_t d, const void* s, int sz) {
    asm volatile("cp.async.cg.shared.global [%0], [%1], 16, %2;"
                 :: "r"(d), "l"(s), "r"(sz) : "memory");
}
__device__ __forceinline__ void cp_commit() {
    asm volatile("cp.async.commit_group;" ::: "memory");
}
template <int N> __device__ __forceinline__ void cp_wait() {
    asm volatile("cp.async.wait_group %0;" :: "n"(N) : "memory");
}
__device__ __forceinline__ void ldsm4(uint32_t* r, uint32_t a) {
    asm volatile("ldmatrix.sync.aligned.m8n8.x4.shared.b16 {%0,%1,%2,%3}, [%4];"
                 : "=r"(r[0]), "=r"(r[1]), "=r"(r[2]), "=r"(r[3]) : "r"(a));
}
__device__ __forceinline__ void mma16816(float* d, const uint32_t* a,
                                         const uint32_t* b) {
    asm volatile(
        "mma.sync.aligned.m16n8k16.row.col.f32.bf16.bf16.f32 "
        "{%0,%1,%2,%3}, {%4,%5,%6,%7}, {%8,%9}, {%0,%1,%2,%3};"
        : "+f"(d[0]), "+f"(d[1]), "+f"(d[2]), "+f"(d[3])
        : "r"(a[0]), "r"(a[1]), "r"(a[2]), "r"(a[3]), "r"(b[0]), "r"(b[1]));
}

// ------------------------------- GEMM kernel --------------------------------
// D[M, Ntot] = split3(A[M,K]) @ split3(B[Ntot,K])^T + bias; optional lrelu.
// BM=128, BN=256, BK=64. 16 warps: warp tile 64x32 (warp_m 2 x warp_n 8).
__global__ void __launch_bounds__(NTHREADS, 1)
gemm_bf16x3(const __nv_bfloat16* __restrict__ Ahi, const __nv_bfloat16* __restrict__ Alo,
            const __nv_bfloat16* __restrict__ Bhi, const __nv_bfloat16* __restrict__ Blo,
            const float* __restrict__ bias,
            __nv_bfloat16* __restrict__ Chi, __nv_bfloat16* __restrict__ Clo,
            float* __restrict__ Yout,
            int K, int Ntot, int act, int f32out)
{
    extern __shared__ char sm[];
    const uint32_t sbase = smem_u32(sm);

    const int tid  = threadIdx.x;
    const int wid  = tid >> 5;
    const int lane = tid & 31;
    const int warp_m = wid & 1;        // 2 x 64 rows
    const int warp_n = wid >> 1;       // 8 x 32 cols
    const int m0 = blockIdx.y * 128;
    const int n0 = blockIdx.x * 256;

    float acc[4][4][4];
#pragma unroll
    for (int i = 0; i < 4; i++)
#pragma unroll
        for (int j = 0; j < 4; j++)
#pragma unroll
            for (int k = 0; k < 4; k++) acc[i][j][k] = 0.f;

    const int kn = K >> 6;             // BK = 64

    // ldmatrix per-lane offsets (bytes, within a stage)
    const uint32_t a_off = (uint32_t)((warp_m * 64 + (lane & 15)) * PITCH
                                      + (lane >> 4) * 16);
    const uint32_t b_off = (uint32_t)((warp_n * 32 + (lane & 7) + ((lane >> 4) << 3)) * PITCH
                                      + ((lane >> 3) & 1) * 16);

    // cp.async (512 threads): A tiles 1024 chunks -> 2/thread; B 2048 -> 4/thread.
#define LOAD_STAGE(KS, BUF)                                                          \
    {                                                                                \
        const int k0_ = (KS) << 6;                                                   \
        const uint32_t sb_ = sbase + (BUF) * STAGE;                                  \
        _Pragma("unroll")                                                            \
        for (int j_ = 0; j_ < 2; j_++) {                                             \
            int slot_ = tid + j_ * NTHREADS;                                         \
            int row_ = slot_ >> 3;                                                   \
            int col_ = slot_ & 7;                                                    \
            uint32_t d_ = sb_ + (uint32_t)(row_ * PITCH + col_ * 16);                \
            size_t ga_ = (size_t)(m0 + row_) * K + k0_ + col_ * 8;                   \
            cp16(d_ + OFF_AH, Ahi + ga_, 16);                                        \
            cp16(d_ + OFF_AL, Alo + ga_, 16);                                        \
        }                                                                            \
        _Pragma("unroll")                                                            \
        for (int j_ = 0; j_ < 4; j_++) {                                             \
            int slot_ = tid + j_ * NTHREADS;                                         \
            int row_ = slot_ >> 3;                                                   \
            int col_ = slot_ & 7;                                                    \
            uint32_t d_ = sb_ + (uint32_t)(row_ * PITCH + col_ * 16);                \
            int n_ = n0 + row_;                                                      \
            int sz_ = (n_ < Ntot) ? 16 : 0;                                          \
            int nc_ = (n_ < Ntot) ? n_ : (Ntot - 1);                                 \
            size_t gb_ = (size_t)nc_ * K + k0_ + col_ * 8;                           \
            cp16(d_ + OFF_BH, Bhi + gb_, sz_);                                       \
            cp16(d_ + OFF_BL, Blo + gb_, sz_);                                       \
        }                                                                            \
    }

    LOAD_STAGE(0, 0); cp_commit();

    for (int ks = 0; ks < kn; ks++) {
        if (ks + 1 < kn) {
            LOAD_STAGE(ks + 1, (ks + 1) & 1); cp_commit(); cp_wait<1>();
        } else {
            cp_wait<0>();
        }
        __syncthreads();

        const uint32_t sb = sbase + (ks & 1) * STAGE;
#pragma unroll
        for (int kk = 0; kk < 4; kk++) {           // 4 x K16 per stage
            uint32_t ah[4][4], al[4][4], bh[4][2], bl[4][2];
#pragma unroll
            for (int mt = 0; mt < 4; mt++) {
                uint32_t o = a_off + (uint32_t)(mt * 16 * PITCH + kk * 32);
                ldsm4(ah[mt], sb + OFF_AH + o);
                ldsm4(al[mt], sb + OFF_AL + o);
            }
#pragma unroll
            for (int np = 0; np < 2; np++) {       // 2 x 16-col B panels
                uint32_t o = b_off + (uint32_t)(np * 16 * PITCH + kk * 32);
                uint32_t r[4];
                ldsm4(r, sb + OFF_BH + o);
                bh[2 * np][0] = r[0]; bh[2 * np][1] = r[1];
                bh[2 * np + 1][0] = r[2]; bh[2 * np + 1][1] = r[3];
                ldsm4(r, sb + OFF_BL + o);
                bl[2 * np][0] = r[0]; bl[2 * np][1] = r[1];
                bl[2 * np + 1][0] = r[2]; bl[2 * np + 1][1] = r[3];
            }
            // Per-accumulator term order hh -> hl -> lh (bitwise-stable).
#pragma unroll
            for (int mt = 0; mt < 4; mt++)
#pragma unroll
                for (int nt = 0; nt < 4; nt++) {
                    mma16816(acc[mt][nt], ah[mt], bh[nt]);
                    mma16816(acc[mt][nt], ah[mt], bl[nt]);
                    mma16816(acc[mt][nt], al[mt], bh[nt]);
                }
        }
        if (ks + 1 < kn) __syncthreads();   // protect buf before next overwrite
    }

    // ---- epilogue: bias + act, write split-bf16 or fp32 ----
    const int mrow = lane >> 2;
    const int ncol = (lane & 3) * 2;
#pragma unroll
    for (int mt = 0; mt < 4; mt++) {
#pragma unroll
        for (int nt = 0; nt < 4; nt++) {
            int n = n0 + warp_n * 32 + nt * 8 + ncol;
            if (n >= Ntot) continue;
            float bs0 = __ldg(bias + n);
            float bs1 = __ldg(bias + n + 1);
#pragma unroll
            for (int half = 0; half < 2; half++) {
                int m = m0 + warp_m * 64 + mt * 16 + mrow + half * 8;
                float v0 = acc[mt][nt][half * 2]     + bs0;
                float v1 = acc[mt][nt][half * 2 + 1] + bs1;
                if (act) {
                    v0 = v0 > 0.f ? v0 : 0.01f * v0;
                    v1 = v1 > 0.f ? v1 : 0.01f * v1;
                }
                if (f32out) {
                    *(float2*)(Yout + (size_t)m * Ntot + n) = make_float2(v0, v1);
                } else {
                    __nv_bfloat16 h0 = __float2bfloat16(v0);
                    __nv_bfloat16 h1 = __float2bfloat16(v1);
                    __nv_bfloat16 l0 = __float2bfloat16(v0 - __bfloat162float(h0));
                    __nv_bfloat16 l1 = __float2bfloat16(v1 - __bfloat162float(h1));
                    *(__nv_bfloat162*)(Chi + (size_t)m * Ntot + n) = __halves2bfloat162(h0, h1);
                    *(__nv_bfloat162*)(Clo + (size_t)m * Ntot + n) = __halves2bfloat162(l0, l1);
                }
            }
        }
    }
}

// --------------------------- split / transpose ------------------------------
__global__ void split_f32_kernel(const float* __restrict__ in,
                                 __nv_bfloat16* __restrict__ hi,
                                 __nv_bfloat16* __restrict__ lo, int n4)
{
    int i = blockIdx.x * blockDim.x + threadIdx.x;
    if (i < n4) {
        float4 v = ((const float4*)in)[i];
        __nv_bfloat16 h0 = __float2bfloat16(v.x), h1 = __float2bfloat16(v.y);
        __nv_bfloat16 h2 = __float2bfloat16(v.z), h3 = __float2bfloat16(v.w);
        __nv_bfloat16 l0 = __float2bfloat16(v.x - __bfloat162float(h0));
        __nv_bfloat16 l1 = __float2bfloat16(v.y - __bfloat162float(h1));
        __nv_bfloat16 l2 = __float2bfloat16(v.z - __bfloat162float(h2));
        __nv_bfloat16 l3 = __float2bfloat16(v.w - __bfloat162float(h3));
        ((__nv_bfloat162*)hi)[i * 2]     = __halves2bfloat162(h0, h1);
        ((__nv_bfloat162*)hi)[i * 2 + 1] = __halves2bfloat162(h2, h3);
        ((__nv_bfloat162*)lo)[i * 2]     = __halves2bfloat162(l0, l1);
        ((__nv_bfloat162*)lo)[i * 2 + 1] = __halves2bfloat162(l2, l3);
    }
}

// W[K,N] fp32 -> BT[N,K] bf16 hi/lo (transpose + split). Dims %32 == 0.
__global__ void wsplit_t_kernel(const float* __restrict__ W,
                                __nv_bfloat16* __restrict__ bth,
                                __nv_bfloat16* __restrict__ btl, int K, int N)
{
    __shared__ float t[32][33];
    const int n0 = blockIdx.x * 32, k0 = blockIdx.y * 32;
    const int tx = threadIdx.x, ty = threadIdx.y;
#pragma unroll
    for (int i = 0; i < 32; i += 8)
        t[ty + i][tx] = W[(size_t)(k0 + ty + i) * N + n0 + tx];
    __syncthreads();
#pragma unroll
    for (int i = 0; i < 32; i += 8) {
        float v = t[tx][ty + i];                 // element (k0+tx, n0+ty+i)
        __nv_bfloat16 h = __float2bfloat16(v);
        __nv_bfloat16 l = __float2bfloat16(v - __bfloat162float(h));
        size_t o = (size_t)(n0 + ty + i) * K + k0 + tx;
        bth[o] = h;
        btl[o] = l;
    }
}

// ------------------------------- scatter ------------------------------------
// Writes upper-tri values AND mirrored lower-tri zeros (no separate memset).
__global__ void scatter_tri(const float* __restrict__ y, float* __restrict__ out)
{
    __shared__ float tile[32][33];
    const int l0 = blockIdx.x * 32;
    const int b0 = blockIdx.y * 32;
    const int txi = threadIdx.x;
    const int tyi = threadIdx.y;

#pragma unroll
    for (int i = 0; i < 32; i += 8)
        tile[tyi + i][txi] = y[(size_t)(b0 + tyi + i) * LOUT + l0 + txi];
    __syncthreads();

#pragma unroll
    for (int i = 0; i < 32; i += 8) {
        int l = l0 + tyi + i;
        float disc = 16641.0f - 8.0f * (float)l;
        int r = (int)((129.0f - sqrtf(disc)) * 0.5f);
        if (r < 0) r = 0;
        if (r > 63) r = 63;
        while (r < 63 && (r + 1) * (129 - (r + 1)) / 2 <= l) r++;
        while (r > 0 && r * (129 - r) / 2 > l) r--;
        int c = 63 - (l - r * (129 - r) / 2);
        float v = tile[txi][tyi + i];            // transposed read
        if (r == c && v <= 0.f) v = -v;
        out[((size_t)(r * CPV + c)) * BATCH + b0 + txi] = v;
        if (r != c)                              // mirrored zero (lower tri)
            out[((size_t)(c * CPV + r)) * BATCH + b0 + txi] = 0.f;
    }
}

// ------------------------------- launcher -----------------------------------
extern "C" void kernel_launch(void* const* d_in, const int* in_sizes, int n_in,
                              void* d_out, int out_size)
{
    // Identify inputs by element count (robust to metadata ordering).
    const float *x = 0, *W1 = 0, *W2 = 0, *W21 = 0, *W22 = 0, *W3 = 0;
    const float *b1 = 0, *b2 = 0, *b21 = 0, *b22 = 0, *b3 = 0;
    int nhh = 0, nbb = 0;
    for (int i = 0; i < n_in; i++) {
        const float* p = (const float*)d_in[i];
        switch (in_sizes[i]) {
            case 8388608: x  = p; break;
            case 2097152: W1 = p; break;
            case 4259840: W3 = p; break;
            case 2080:    b3 = p; break;
            case 4194304:
                if      (nhh == 0) W2  = p;
                else if (nhh == 1) W21 = p;
                else               W22 = p;
                nhh++; break;
            case 2048:
                if      (nbb == 0) b1  = p;
                else if (nbb == 1) b2  = p;
                else if (nbb == 2) b21 = p;
                else               b22 = p;
                nbb++; break;
            default: break;
        }
    }

    void *pAh0, *pAl0, *pAh1, *pAl1, *pW1h, *pW1l, *pW2h, *pW2l;
    void *pW21h, *pW21l, *pW22h, *pW22l, *pW3h, *pW3l, *pY;
    cudaGetSymbolAddress(&pAh0, g_Ah0);   cudaGetSymbolAddress(&pAl0, g_Al0);
    cudaGetSymbolAddress(&pAh1, g_Ah1);   cudaGetSymbolAddress(&pAl1, g_Al1);
    cudaGetSymbolAddress(&pW1h, g_W1h);   cudaGetSymbolAddress(&pW1l, g_W1l);
    cudaGetSymbolAddress(&pW2h, g_W2h);   cudaGetSymbolAddress(&pW2l, g_W2l);
    cudaGetSymbolAddress(&pW21h, g_W21h); cudaGetSymbolAddress(&pW21l, g_W21l);
    cudaGetSymbolAddress(&pW22h, g_W22h); cudaGetSymbolAddress(&pW22l, g_W22l);
    cudaGetSymbolAddress(&pW3h, g_W3h);   cudaGetSymbolAddress(&pW3l, g_W3l);
    cudaGetSymbolAddress(&pY, g_Y);
    __nv_bfloat16 *Ah0 = (__nv_bfloat16*)pAh0, *Al0 = (__nv_bfloat16*)pAl0;
    __nv_bfloat16 *Ah1 = (__nv_bfloat16*)pAh1, *Al1 = (__nv_bfloat16*)pAl1;
    __nv_bfloat16 *W1h = (__nv_bfloat16*)pW1h, *W1l = (__nv_bfloat16*)pW1l;
    __nv_bfloat16 *W2h = (__nv_bfloat16*)pW2h, *W2l = (__nv_bfloat16*)pW2l;
    __nv_bfloat16 *W21h = (__nv_bfloat16*)pW21h, *W21l = (__nv_bfloat16*)pW21l;
    __nv_bfloat16 *W22h = (__nv_bfloat16*)pW22h, *W22l = (__nv_bfloat16*)pW22l;
    __nv_bfloat16 *W3h = (__nv_bfloat16*)pW3h, *W3l = (__nv_bfloat16*)pW3l;
    float* Y = (float*)pY;

    cudaFuncSetAttribute(gemm_bf16x3,
                         cudaFuncAttributeMaxDynamicSharedMemorySize, SMEMSZ);

    dim3 tb(32, 8);
    dim3 blk(NTHREADS);
    dim3 gH(HID / 256, BATCH / 128);                     // (8, 64)
    dim3 gL((LOUT + 255) / 256, BATCH / 128);            // (9, 64)

    split_f32_kernel<<<(BATCH * DIN / 4 + 255) / 256, 256>>>(x, Ah0, Al0, BATCH * DIN / 4);
    wsplit_t_kernel<<<dim3(HID / 32, DIN / 32), tb>>>(W1, W1h, W1l, DIN, HID);
    wsplit_t_kernel<<<dim3(HID / 32, HID / 32), tb>>>(W2, W2h, W2l, HID, HID);
    wsplit_t_kernel<<<dim3(HID / 32, HID / 32), tb>>>(W21, W21h, W21l, HID, HID);
    wsplit_t_kernel<<<dim3(HID / 32, HID / 32), tb>>>(W22, W22h, W22l, HID, HID);

    gemm_bf16x3<<<gH, blk, SMEMSZ>>>(Ah0, Al0, W1h, W1l, b1, Ah1, Al1, 0, DIN, HID, 1, 0);
    gemm_bf16x3<<<gH, blk, SMEMSZ>>>(Ah1, Al1, W2h, W2l, b2, Ah0, Al0, 0, HID, HID, 1, 0);
    gemm_bf16x3<<<gH, blk, SMEMSZ>>>(Ah0, Al0, W21h, W21l, b21, Ah1, Al1, 0, HID, HID, 1, 0);
    gemm_bf16x3<<<gH, blk, SMEMSZ>>>(Ah1, Al1, W22h, W22l, b22, Ah0, Al0, 0, HID, HID, 1, 0);

    wsplit_t_kernel<<<dim3(LOUT / 32, HID / 32), tb>>>(W3, W3h, W3l, HID, LOUT);
    gemm_bf16x3<<<gL, blk, SMEMSZ>>>(Ah0, Al0, W3h, W3l, b3, 0, 0, Y, HID, LOUT, 0, 1);

    dim3 gsc(LOUT / 32, BATCH / 32);
    dim3 bsc(32, 8);
    scatter_tri<<<gsc, bsc>>>(Y, (float*)d_out);   // includes lower-tri zeros
}

// round 12
// speedup vs baseline: 2.1487x; 2.1487x over previous
#include <cuda_runtime.h>
#include <cuda_fp16.h>
#include <cstdint>

// ============================================================================
// ModelR: x[8192,1024] -> (Linear+LeakyReLU) x4 -> Linear -> tri-scatter
// Round 12: flop cut 3->2 MMA terms via fp16 split.
//   D = Ah@B + Al@B   (A split into fp16 hi/lo, residual 2^-22;
//                      B single fp16, rounding 2^-12 dominates error)
// Predicted rel_err ~3-6e-4 (<1e-3). GEMM structure = proven R8 config:
// BM=128, BN=128, BK=64, 256 thr, 3-stage cp.async, pitch 144B.
// Stage now 3 tiles (Ah, Al, B) = 55296B; 3 stages = 165888B, 1 CTA/SM.
// Memset fused into scatter (mirrored zeros), verified in R11.
// ============================================================================

#define BATCH 8192
#define DIN   1024
#define HID   2048
#define LOUT  2080
#define CPV   64

#define PITCH   144         // 128B payload (64 fp16) + 16B pad
#define OFF_AH  0
#define OFF_AL  18432       // 128 rows * 144B
#define OFF_B   36864
#define STAGE   55296
#define NSTAGE  3
#define SMEMSZ  (NSTAGE * STAGE)   // 165888 B

// ------------------------- device scratch (no allocs) -----------------------
__device__ __half g_Ah0[(size_t)BATCH * HID];
__device__ __half g_Al0[(size_t)BATCH * HID];
__device__ __half g_Ah1[(size_t)BATCH * HID];
__device__ __half g_Al1[(size_t)BATCH * HID];
__device__ __half g_W1t[(size_t)HID * DIN];
__device__ __half g_W2t[(size_t)HID * HID];
__device__ __half g_W21t[(size_t)HID * HID];
__device__ __half g_W22t[(size_t)HID * HID];
__device__ __half g_W3t[(size_t)LOUT * HID];
__device__ float  g_Y[(size_t)BATCH * LOUT];

// ------------------------------ PTX helpers ---------------------------------
__device__ __forceinline__ uint32_t smem_u32(const void* p) {
    uint32_t a;
    asm("{ .reg .u64 t; cvta.to.shared.u64 t, %1; cvt.u32.u64 %0, t; }"
        : "=r"(a) : "l"(p));
    return a;
}
__device__ __forceinline__ void cp16(uint32_t d, const void* s, int sz) {
    asm volatile("cp.async.cg.shared.global [%0], [%1], 16, %2;"
                 :: "r"(d), "l"(s), "r"(sz) : "memory");
}
__device__ __forceinline__ void cp_commit() {
    asm volatile("cp.async.commit_group;" ::: "memory");
}
template <int N> __device__ __forceinline__ void cp_wait() {
    asm volatile("cp.async.wait_group %0;" :: "n"(N) : "memory");
}
__device__ __forceinline__ void ldsm4(uint32_t* r, uint32_t a) {
    asm volatile("ldmatrix.sync.aligned.m8n8.x4.shared.b16 {%0,%1,%2,%3}, [%4];"
                 : "=r"(r[0]), "=r"(r[1]), "=r"(r[2]), "=r"(r[3]) : "r"(a));
}
__device__ __forceinline__ void mma16816(float* d, const uint32_t* a,
                                         const uint32_t* b) {
    asm volatile(
        "mma.sync.aligned.m16n8k16.row.col.f32.f16.f16.f32 "
        "{%0,%1,%2,%3}, {%4,%5,%6,%7}, {%8,%9}, {%0,%1,%2,%3};"
        : "+f"(d[0]), "+f"(d[1]), "+f"(d[2]), "+f"(d[3])
        : "r"(a[0]), "r"(a[1]), "r"(a[2]), "r"(a[3]), "r"(b[0]), "r"(b[1]));
}

// ------------------------------- GEMM kernel --------------------------------
// D[M, Ntot] = (Ah + Al)[M,K] @ B[Ntot,K]^T + bias; optional lrelu.
// BM=128, BN=128, BK=64. 8 warps: warp tile 64x32 (warp_m 2 x warp_n 4).
__global__ void __launch_bounds__(256, 1)
gemm_f16x2(const __half* __restrict__ Ahi, const __half* __restrict__ Alo,
           const __half* __restrict__ B,
           const float* __restrict__ bias,
           __half* __restrict__ Chi, __half* __restrict__ Clo,
           float* __restrict__ Yout,
           int K, int Ntot, int act, int f32out)
{
    extern __shared__ char sm[];
    const uint32_t sbase = smem_u32(sm);

    const int tid  = threadIdx.x;
    const int wid  = tid >> 5;
    const int lane = tid & 31;
    const int warp_m = wid & 1;        // 2 x 64 rows
    const int warp_n = wid >> 1;       // 4 x 32 cols
    const int m0 = blockIdx.y * 128;
    const int n0 = blockIdx.x * 128;

    float acc[4][4][4];
#pragma unroll
    for (int i = 0; i < 4; i++)
#pragma unroll
        for (int j = 0; j < 4; j++)
#pragma unroll
            for (int k = 0; k < 4; k++) acc[i][j][k] = 0.f;

    const int kn = K >> 6;             // BK = 64

    // ldmatrix per-lane offsets (bytes, within a stage)
    const uint32_t a_off = (uint32_t)((warp_m * 64 + (lane & 15)) * PITCH
                                      + (lane >> 4) * 16);
    const uint32_t b_off = (uint32_t)((warp_n * 32 + (lane & 7) + ((lane >> 4) << 3)) * PITCH
                                      + ((lane >> 3) & 1) * 16);

    // cp.async: 3 tiles (Ah/Al/B), each 128 rows x 8 x 16B chunks = 1024;
    // 256 threads -> 4 chunks/thread/tile (12 cp16 per stage).
#define LOAD_STAGE(KS, BUF)                                                          \
    {                                                                                \
        const int k0_ = (KS) << 6;                                                   \
        const uint32_t sb_ = sbase + (BUF) * STAGE;                                  \
        _Pragma("unroll")                                                            \
        for (int j_ = 0; j_ < 4; j_++) {                                             \
            int slot_ = tid + j_ * 256;                                              \
            int row_ = slot_ >> 3;                                                   \
            int col_ = slot_ & 7;                                                    \
            uint32_t d_ = sb_ + (uint32_t)(row_ * PITCH + col_ * 16);                \
            size_t ga_ = (size_t)(m0 + row_) * K + k0_ + col_ * 8;                   \
            cp16(d_ + OFF_AH, Ahi + ga_, 16);                                        \
            cp16(d_ + OFF_AL, Alo + ga_, 16);                                        \
            int n_ = n0 + row_;                                                      \
            int sz_ = (n_ < Ntot) ? 16 : 0;                                          \
            int nc_ = (n_ < Ntot) ? n_ : (Ntot - 1);                                 \
            size_t gb_ = (size_t)nc_ * K + k0_ + col_ * 8;                           \
            cp16(d_ + OFF_B, B + gb_, sz_);                                          \
        }                                                                            \
    }

    // prologue: stages 0, 1
    LOAD_STAGE(0, 0); cp_commit();
    if (kn > 1) { LOAD_STAGE(1, 1); cp_commit(); }

    for (int ks = 0; ks < kn; ks++) {
        const int buf = ks % 3;
        if (ks + 2 < kn) {
            LOAD_STAGE(ks + 2, (ks + 2) % 3); cp_commit(); cp_wait<2>();
        } else if (ks + 1 < kn) {
            cp_wait<1>();
        } else {
            cp_wait<0>();
        }
        __syncthreads();

        const uint32_t sb = sbase + buf * STAGE;
#pragma unroll
        for (int kk = 0; kk < 4; kk++) {           // 4 x K16 per stage
            uint32_t ah[4][4], al[4][4], bh[4][2];
#pragma unroll
            for (int mt = 0; mt < 4; mt++) {
                uint32_t o = a_off + (uint32_t)(mt * 16 * PITCH + kk * 32);
                ldsm4(ah[mt], sb + OFF_AH + o);
                ldsm4(al[mt], sb + OFF_AL + o);
            }
#pragma unroll
            for (int np = 0; np < 2; np++) {
                uint32_t o = b_off + (uint32_t)(np * 16 * PITCH + kk * 32);
                uint32_t r[4];
                ldsm4(r, sb + OFF_B + o);
                bh[2 * np][0] = r[0]; bh[2 * np][1] = r[1];
                bh[2 * np + 1][0] = r[2]; bh[2 * np + 1][1] = r[3];
            }
            // Per-accumulator term order: hi then lo (fixed for determinism).
#pragma unroll
            for (int mt = 0; mt < 4; mt++)
#pragma unroll
                for (int nt = 0; nt < 4; nt++) {
                    mma16816(acc[mt][nt], ah[mt], bh[nt]);
                    mma16816(acc[mt][nt], al[mt], bh[nt]);
                }
        }
        __syncthreads();
    }

    // ---- epilogue: bias + act, write split-fp16 or fp32 ----
    const int mrow = lane >> 2;
    const int ncol = (lane & 3) * 2;
#pragma unroll
    for (int mt = 0; mt < 4; mt++) {
#pragma unroll
        for (int nt = 0; nt < 4; nt++) {
            int n = n0 + warp_n * 32 + nt * 8 + ncol;
            if (n >= Ntot) continue;
            float bs0 = __ldg(bias + n);
            float bs1 = __ldg(bias + n + 1);
#pragma unroll
            for (int half_ = 0; half_ < 2; half_++) {
                int m = m0 + warp_m * 64 + mt * 16 + mrow + half_ * 8;
                float v0 = acc[mt][nt][half_ * 2]     + bs0;
                float v1 = acc[mt][nt][half_ * 2 + 1] + bs1;
                if (act) {
                    v0 = v0 > 0.f ? v0 : 0.01f * v0;
                    v1 = v1 > 0.f ? v1 : 0.01f * v1;
                }
                if (f32out) {
                    *(float2*)(Yout + (size_t)m * Ntot + n) = make_float2(v0, v1);
                } else {
                    __half h0 = __float2half_rn(v0);
                    __half h1 = __float2half_rn(v1);
                    __half l0 = __float2half_rn(v0 - __half2float(h0));
                    __half l1 = __float2half_rn(v1 - __half2float(h1));
                    *(__half2*)(Chi + (size_t)m * Ntot + n) = __halves2half2(h0, h1);
                    *(__half2*)(Clo + (size_t)m * Ntot + n) = __halves2half2(l0, l1);
                }
            }
        }
    }
}

// --------------------------- split / transpose ------------------------------
// x fp32 -> fp16 hi/lo, elementwise (float4-vectorized)
__global__ void split_f32_kernel(const float* __restrict__ in,
                                 __half* __restrict__ hi,
                                 __half* __restrict__ lo, int n4)
{
    int i = blockIdx.x * blockDim.x + threadIdx.x;
    if (i < n4) {
        float4 v = ((const float4*)in)[i];
        __half h0 = __float2half_rn(v.x), h1 = __float2half_rn(v.y);
        __half h2 = __float2half_rn(v.z), h3 = __float2half_rn(v.w);
        __half l0 = __float2half_rn(v.x - __half2float(h0));
        __half l1 = __float2half_rn(v.y - __half2float(h1));
        __half l2 = __float2half_rn(v.z - __half2float(h2));
        __half l3 = __float2half_rn(v.w - __half2float(h3));
        ((__half2*)hi)[i * 2]     = __halves2half2(h0, h1);
        ((__half2*)hi)[i * 2 + 1] = __halves2half2(h2, h3);
        ((__half2*)lo)[i * 2]     = __halves2half2(l0, l1);
        ((__half2*)lo)[i * 2 + 1] = __halves2half2(l2, l3);
    }
}

// W[K,N] fp32 -> BT[N,K] single fp16 (transpose). Dims %32 == 0.
__global__ void wsplit_t_kernel(const float* __restrict__ W,
                                __half* __restrict__ bt, int K, int N)
{
    __shared__ float t[32][33];
    const int n0 = blockIdx.x * 32, k0 = blockIdx.y * 32;
    const int tx = threadIdx.x, ty = threadIdx.y;
#pragma unroll
    for (int i = 0; i < 32; i += 8)
        t[ty + i][tx] = W[(size_t)(k0 + ty + i) * N + n0 + tx];
    __syncthreads();
#pragma unroll
    for (int i = 0; i < 32; i += 8) {
        float v = t[tx][ty + i];                 // element (k0+tx, n0+ty+i)
        bt[(size_t)(n0 + ty + i) * K + k0 + tx] = __float2half_rn(v);
    }
}

// ------------------------------- scatter ------------------------------------
// Writes upper-tri values AND mirrored lower-tri zeros (no separate memset).
__global__ void scatter_tri(const float* __restrict__ y, float* __restrict__ out)
{
    __shared__ float tile[32][33];
    const int l0 = blockIdx.x * 32;
    const int b0 = blockIdx.y * 32;
    const int txi = threadIdx.x;
    const int tyi = threadIdx.y;

#pragma unroll
    for (int i = 0; i < 32; i += 8)
        tile[tyi + i][txi] = y[(size_t)(b0 + tyi + i) * LOUT + l0 + txi];
    __syncthreads();

#pragma unroll
    for (int i = 0; i < 32; i += 8) {
        int l = l0 + tyi + i;
        float disc = 16641.0f - 8.0f * (float)l;
        int r = (int)((129.0f - sqrtf(disc)) * 0.5f);
        if (r < 0) r = 0;
        if (r > 63) r = 63;
        while (r < 63 && (r + 1) * (129 - (r + 1)) / 2 <= l) r++;
        while (r > 0 && r * (129 - r) / 2 > l) r--;
        int c = 63 - (l - r * (129 - r) / 2);
        float v = tile[txi][tyi + i];            // transposed read
        if (r == c && v <= 0.f) v = -v;
        out[((size_t)(r * CPV + c)) * BATCH + b0 + txi] = v;
        if (r != c)                              // mirrored zero (lower tri)
            out[((size_t)(c * CPV + r)) * BATCH + b0 + txi] = 0.f;
    }
}

// ------------------------------- launcher -----------------------------------
extern "C" void kernel_launch(void* const* d_in, const int* in_sizes, int n_in,
                              void* d_out, int out_size)
{
    // Identify inputs by element count (robust to metadata ordering).
    const float *x = 0, *W1 = 0, *W2 = 0, *W21 = 0, *W22 = 0, *W3 = 0;
    const float *b1 = 0, *b2 = 0, *b21 = 0, *b22 = 0, *b3 = 0;
    int nhh = 0, nbb = 0;
    for (int i = 0; i < n_in; i++) {
        const float* p = (const float*)d_in[i];
        switch (in_sizes[i]) {
            case 8388608: x  = p; break;
            case 2097152: W1 = p; break;
            case 4259840: W3 = p; break;
            case 2080:    b3 = p; break;
            case 4194304:
                if      (nhh == 0) W2  = p;
                else if (nhh == 1) W21 = p;
                else               W22 = p;
                nhh++; break;
            case 2048:
                if      (nbb == 0) b1  = p;
                else if (nbb == 1) b2  = p;
                else if (nbb == 2) b21 = p;
                else               b22 = p;
                nbb++; break;
            default: break;
        }
    }

    void *pAh0, *pAl0, *pAh1, *pAl1, *pW1, *pW2, *pW21, *pW22, *pW3, *pY;
    cudaGetSymbolAddress(&pAh0, g_Ah0);  cudaGetSymbolAddress(&pAl0, g_Al0);
    cudaGetSymbolAddress(&pAh1, g_Ah1);  cudaGetSymbolAddress(&pAl1, g_Al1);
    cudaGetSymbolAddress(&pW1, g_W1t);   cudaGetSymbolAddress(&pW2, g_W2t);
    cudaGetSymbolAddress(&pW21, g_W21t); cudaGetSymbolAddress(&pW22, g_W22t);
    cudaGetSymbolAddress(&pW3, g_W3t);   cudaGetSymbolAddress(&pY, g_Y);
    __half *Ah0 = (__half*)pAh0, *Al0 = (__half*)pAl0;
    __half *Ah1 = (__half*)pAh1, *Al1 = (__half*)pAl1;
    __half *W1t = (__half*)pW1, *W2t = (__half*)pW2;
    __half *W21t = (__half*)pW21, *W22t = (__half*)pW22, *W3t = (__half*)pW3;
    float* Y = (float*)pY;

    cudaFuncSetAttribute(gemm_f16x2,
                         cudaFuncAttributeMaxDynamicSharedMemorySize, SMEMSZ);

    dim3 tb(32, 8);
    dim3 blk(256);
    dim3 gH(HID / 128, BATCH / 128);                     // (16, 64)
    dim3 gL((LOUT + 127) / 128, BATCH / 128);            // (17, 64)

    split_f32_kernel<<<(BATCH * DIN / 4 + 255) / 256, 256>>>(x, Ah0, Al0, BATCH * DIN / 4);
    wsplit_t_kernel<<<dim3(HID / 32, DIN / 32), tb>>>(W1, W1t, DIN, HID);
    wsplit_t_kernel<<<dim3(HID / 32, HID / 32), tb>>>(W2, W2t, HID, HID);
    wsplit_t_kernel<<<dim3(HID / 32, HID / 32), tb>>>(W21, W21t, HID, HID);
    wsplit_t_kernel<<<dim3(HID / 32, HID / 32), tb>>>(W22, W22t, HID, HID);
    wsplit_t_kernel<<<dim3(LOUT / 32, HID / 32), tb>>>(W3, W3t, HID, LOUT);

    gemm_f16x2<<<gH, blk, SMEMSZ>>>(Ah0, Al0, W1t, b1, Ah1, Al1, 0, DIN, HID, 1, 0);
    gemm_f16x2<<<gH, blk, SMEMSZ>>>(Ah1, Al1, W2t, b2, Ah0, Al0, 0, HID, HID, 1, 0);
    gemm_f16x2<<<gH, blk, SMEMSZ>>>(Ah0, Al0, W21t, b21, Ah1, Al1, 0, HID, HID, 1, 0);
    gemm_f16x2<<<gH, blk, SMEMSZ>>>(Ah1, Al1, W22t, b22, Ah0, Al0, 0, HID, HID, 1, 0);
    gemm_f16x2<<<gL, blk, SMEMSZ>>>(Ah0, Al0, W3t, b3, 0, 0, Y, HID, LOUT, 0, 1);

    dim3 gsc(LOUT / 32, BATCH / 32);
    dim3 bsc(32, 8);
    scatter_tri<<<gsc, bsc>>>(Y, (float*)d_out);   // includes lower-tri zeros
}

// round 13
// speedup vs baseline: 3.4385x; 1.6003x over previous
#include <cuda_runtime.h>
#include <cuda_fp16.h>
#include <cstdint>

// ============================================================================
// ModelR: x[8192,1024] -> (Linear+LeakyReLU) x4 -> Linear -> tri-scatter
// Round 13: plain fp16 GEMM (1 MMA term).
//   Error model (calibrated on R12): 2-term = B-rounding only = 4.67e-4;
//   1-term adds equal independent A-rounding => x sqrt(2) ~ 6.6e-4 < 1e-3.
//   Fixed-seed bench => deterministic rel_err.
// GEMM structure = proven R8/R12 config: BM=128, BN=128, BK=64, 256 thr,
// 3-stage cp.async, pitch 144B. Stage = 2 tiles (A, B) = 36864B.
// Activations stored as single fp16 (half the traffic of R12).
// ============================================================================

#define BATCH 8192
#define DIN   1024
#define HID   2048
#define LOUT  2080
#define CPV   64

#define PITCH   144         // 128B payload (64 fp16) + 16B pad
#define OFF_A   0
#define OFF_B   18432       // 128 rows * 144B
#define STAGE   36864
#define NSTAGE  3
#define SMEMSZ  (NSTAGE * STAGE)   // 110592 B

// ------------------------- device scratch (no allocs) -----------------------
__device__ __half g_A0[(size_t)BATCH * HID];
__device__ __half g_A1[(size_t)BATCH * HID];
__device__ __half g_W1t[(size_t)HID * DIN];
__device__ __half g_W2t[(size_t)HID * HID];
__device__ __half g_W21t[(size_t)HID * HID];
__device__ __half g_W22t[(size_t)HID * HID];
__device__ __half g_W3t[(size_t)LOUT * HID];
__device__ float  g_Y[(size_t)BATCH * LOUT];

// ------------------------------ PTX helpers ---------------------------------
__device__ __forceinline__ uint32_t smem_u32(const void* p) {
    uint32_t a;
    asm("{ .reg .u64 t; cvta.to.shared.u64 t, %1; cvt.u32.u64 %0, t; }"
        : "=r"(a) : "l"(p));
    return a;
}
__device__ __forceinline__ void cp16(uint32_t d, const void* s, int sz) {
    asm volatile("cp.async.cg.shared.global [%0], [%1], 16, %2;"
                 :: "r"(d), "l"(s), "r"(sz) : "memory");
}
__device__ __forceinline__ void cp_commit() {
    asm volatile("cp.async.commit_group;" ::: "memory");
}
template <int N> __device__ __forceinline__ void cp_wait() {
    asm volatile("cp.async.wait_group %0;" :: "n"(N) : "memory");
}
__device__ __forceinline__ void ldsm4(uint32_t* r, uint32_t a) {
    asm volatile("ldmatrix.sync.aligned.m8n8.x4.shared.b16 {%0,%1,%2,%3}, [%4];"
                 : "=r"(r[0]), "=r"(r[1]), "=r"(r[2]), "=r"(r[3]) : "r"(a));
}
__device__ __forceinline__ void mma16816(float* d, const uint32_t* a,
                                         const uint32_t* b) {
    asm volatile(
        "mma.sync.aligned.m16n8k16.row.col.f32.f16.f16.f32 "
        "{%0,%1,%2,%3}, {%4,%5,%6,%7}, {%8,%9}, {%0,%1,%2,%3};"
        : "+f"(d[0]), "+f"(d[1]), "+f"(d[2]), "+f"(d[3])
        : "r"(a[0]), "r"(a[1]), "r"(a[2]), "r"(a[3]), "r"(b[0]), "r"(b[1]));
}

// ------------------------------- GEMM kernel --------------------------------
// D[M, Ntot] = A[M,K] @ B[Ntot,K]^T + bias; optional lrelu.
// BM=128, BN=128, BK=64. 8 warps: warp tile 64x32 (warp_m 2 x warp_n 4).
__global__ void __launch_bounds__(256, 1)
gemm_f16(const __half* __restrict__ A, const __half* __restrict__ B,
         const float* __restrict__ bias,
         __half* __restrict__ Cout, float* __restrict__ Yout,
         int K, int Ntot, int act, int f32out)
{
    extern __shared__ char sm[];
    const uint32_t sbase = smem_u32(sm);

    const int tid  = threadIdx.x;
    const int wid  = tid >> 5;
    const int lane = tid & 31;
    const int warp_m = wid & 1;        // 2 x 64 rows
    const int warp_n = wid >> 1;       // 4 x 32 cols
    const int m0 = blockIdx.y * 128;
    const int n0 = blockIdx.x * 128;

    float acc[4][4][4];
#pragma unroll
    for (int i = 0; i < 4; i++)
#pragma unroll
        for (int j = 0; j < 4; j++)
#pragma unroll
            for (int k = 0; k < 4; k++) acc[i][j][k] = 0.f;

    const int kn = K >> 6;             // BK = 64

    // ldmatrix per-lane offsets (bytes, within a stage)
    const uint32_t a_off = (uint32_t)((warp_m * 64 + (lane & 15)) * PITCH
                                      + (lane >> 4) * 16);
    const uint32_t b_off = (uint32_t)((warp_n * 32 + (lane & 7) + ((lane >> 4) << 3)) * PITCH
                                      + ((lane >> 3) & 1) * 16);

    // cp.async: 2 tiles (A/B), each 128 rows x 8 x 16B chunks = 1024;
    // 256 threads -> 4 chunks/thread/tile (8 cp16 per stage).
#define LOAD_STAGE(KS, BUF)                                                          \
    {                                                                                \
        const int k0_ = (KS) << 6;                                                   \
        const uint32_t sb_ = sbase + (BUF) * STAGE;                                  \
        _Pragma("unroll")                                                            \
        for (int j_ = 0; j_ < 4; j_++) {                                             \
            int slot_ = tid + j_ * 256;                                              \
            int row_ = slot_ >> 3;                                                   \
            int col_ = slot_ & 7;                                                    \
            uint32_t d_ = sb_ + (uint32_t)(row_ * PITCH + col_ * 16);                \
            size_t ga_ = (size_t)(m0 + row_) * K + k0_ + col_ * 8;                   \
            cp16(d_ + OFF_A, A + ga_, 16);                                           \
            int n_ = n0 + row_;                                                      \
            int sz_ = (n_ < Ntot) ? 16 : 0;                                          \
            int nc_ = (n_ < Ntot) ? n_ : (Ntot - 1);                                 \
            size_t gb_ = (size_t)nc_ * K + k0_ + col_ * 8;                           \
            cp16(d_ + OFF_B, B + gb_, sz_);                                          \
        }                                                                            \
    }

    // prologue: stages 0, 1
    LOAD_STAGE(0, 0); cp_commit();
    if (kn > 1) { LOAD_STAGE(1, 1); cp_commit(); }

    for (int ks = 0; ks < kn; ks++) {
        const int buf = ks % 3;
        if (ks + 2 < kn) {
            LOAD_STAGE(ks + 2, (ks + 2) % 3); cp_commit(); cp_wait<2>();
        } else if (ks + 1 < kn) {
            cp_wait<1>();
        } else {
            cp_wait<0>();
        }
        __syncthreads();

        const uint32_t sb = sbase + buf * STAGE;
#pragma unroll
        for (int kk = 0; kk < 4; kk++) {           // 4 x K16 per stage
            uint32_t ah[4][4], bh[4][2];
#pragma unroll
            for (int mt = 0; mt < 4; mt++) {
                uint32_t o = a_off + (uint32_t)(mt * 16 * PITCH + kk * 32);
                ldsm4(ah[mt], sb + OFF_A + o);
            }
#pragma unroll
            for (int np = 0; np < 2; np++) {
                uint32_t o = b_off + (uint32_t)(np * 16 * PITCH + kk * 32);
                uint32_t r[4];
                ldsm4(r, sb + OFF_B + o);
                bh[2 * np][0] = r[0]; bh[2 * np][1] = r[1];
                bh[2 * np + 1][0] = r[2]; bh[2 * np + 1][1] = r[3];
            }
#pragma unroll
            for (int mt = 0; mt < 4; mt++)
#pragma unroll
                for (int nt = 0; nt < 4; nt++)
                    mma16816(acc[mt][nt], ah[mt], bh[nt]);
        }
        __syncthreads();
    }

    // ---- epilogue: bias + act, write fp16 or fp32 ----
    const int mrow = lane >> 2;
    const int ncol = (lane & 3) * 2;
#pragma unroll
    for (int mt = 0; mt < 4; mt++) {
#pragma unroll
        for (int nt = 0; nt < 4; nt++) {
            int n = n0 + warp_n * 32 + nt * 8 + ncol;
            if (n >= Ntot) continue;
            float bs0 = __ldg(bias + n);
            float bs1 = __ldg(bias + n + 1);
#pragma unroll
            for (int half_ = 0; half_ < 2; half_++) {
                int m = m0 + warp_m * 64 + mt * 16 + mrow + half_ * 8;
                float v0 = acc[mt][nt][half_ * 2]     + bs0;
                float v1 = acc[mt][nt][half_ * 2 + 1] + bs1;
                if (act) {
                    v0 = v0 > 0.f ? v0 : 0.01f * v0;
                    v1 = v1 > 0.f ? v1 : 0.01f * v1;
                }
                if (f32out) {
                    *(float2*)(Yout + (size_t)m * Ntot + n) = make_float2(v0, v1);
                } else {
                    *(__half2*)(Cout + (size_t)m * Ntot + n) =
                        __halves2half2(__float2half_rn(v0), __float2half_rn(v1));
                }
            }
        }
    }
}

// --------------------------- cast / transpose -------------------------------
// x fp32 -> fp16 (float4-vectorized)
__global__ void cast_f32_f16(const float* __restrict__ in,
                             __half* __restrict__ out, int n4)
{
    int i = blockIdx.x * blockDim.x + threadIdx.x;
    if (i < n4) {
        float4 v = ((const float4*)in)[i];
        ((__half2*)out)[i * 2]     = __halves2half2(__float2half_rn(v.x), __float2half_rn(v.y));
        ((__half2*)out)[i * 2 + 1] = __halves2half2(__float2half_rn(v.z), __float2half_rn(v.w));
    }
}

// W[K,N] fp32 -> BT[N,K] fp16 (transpose). Dims %32 == 0.
__global__ void wsplit_t_kernel(const float* __restrict__ W,
                                __half* __restrict__ bt, int K, int N)
{
    __shared__ float t[32][33];
    const int n0 = blockIdx.x * 32, k0 = blockIdx.y * 32;
    const int tx = threadIdx.x, ty = threadIdx.y;
#pragma unroll
    for (int i = 0; i < 32; i += 8)
        t[ty + i][tx] = W[(size_t)(k0 + ty + i) * N + n0 + tx];
    __syncthreads();
#pragma unroll
    for (int i = 0; i < 32; i += 8) {
        float v = t[tx][ty + i];                 // element (k0+tx, n0+ty+i)
        bt[(size_t)(n0 + ty + i) * K + k0 + tx] = __float2half_rn(v);
    }
}

// ------------------------------- scatter ------------------------------------
// Writes upper-tri values AND mirrored lower-tri zeros (no separate memset).
__global__ void scatter_tri(const float* __restrict__ y, float* __restrict__ out)
{
    __shared__ float tile[32][33];
    const int l0 = blockIdx.x * 32;
    const int b0 = blockIdx.y * 32;
    const int txi = threadIdx.x;
    const int tyi = threadIdx.y;

#pragma unroll
    for (int i = 0; i < 32; i += 8)
        tile[tyi + i][txi] = y[(size_t)(b0 + tyi + i) * LOUT + l0 + txi];
    __syncthreads();

#pragma unroll
    for (int i = 0; i < 32; i += 8) {
        int l = l0 + tyi + i;
        float disc = 16641.0f - 8.0f * (float)l;
        int r = (int)((129.0f - sqrtf(disc)) * 0.5f);
        if (r < 0) r = 0;
        if (r > 63) r = 63;
        while (r < 63 && (r + 1) * (129 - (r + 1)) / 2 <= l) r++;
        while (r > 0 && r * (129 - r) / 2 > l) r--;
        int c = 63 - (l - r * (129 - r) / 2);
        float v = tile[txi][tyi + i];            // transposed read
        if (r == c && v <= 0.f) v = -v;
        out[((size_t)(r * CPV + c)) * BATCH + b0 + txi] = v;
        if (r != c)                              // mirrored zero (lower tri)
            out[((size_t)(c * CPV + r)) * BATCH + b0 + txi] = 0.f;
    }
}

// ------------------------------- launcher -----------------------------------
extern "C" void kernel_launch(void* const* d_in, const int* in_sizes, int n_in,
                              void* d_out, int out_size)
{
    // Identify inputs by element count (robust to metadata ordering).
    const float *x = 0, *W1 = 0, *W2 = 0, *W21 = 0, *W22 = 0, *W3 = 0;
    const float *b1 = 0, *b2 = 0, *b21 = 0, *b22 = 0, *b3 = 0;
    int nhh = 0, nbb = 0;
    for (int i = 0; i < n_in; i++) {
        const float* p = (const float*)d_in[i];
        switch (in_sizes[i]) {
            case 8388608: x  = p; break;
            case 2097152: W1 = p; break;
            case 4259840: W3 = p; break;
            case 2080:    b3 = p; break;
            case 4194304:
                if      (nhh == 0) W2  = p;
                else if (nhh == 1) W21 = p;
                else               W22 = p;
                nhh++; break;
            case 2048:
                if      (nbb == 0) b1  = p;
                else if (nbb == 1) b2  = p;
                else if (nbb == 2) b21 = p;
                else               b22 = p;
                nbb++; break;
            default: break;
        }
    }

    void *pA0, *pA1, *pW1, *pW2, *pW21, *pW22, *pW3, *pY;
    cudaGetSymbolAddress(&pA0, g_A0);    cudaGetSymbolAddress(&pA1, g_A1);
    cudaGetSymbolAddress(&pW1, g_W1t);   cudaGetSymbolAddress(&pW2, g_W2t);
    cudaGetSymbolAddress(&pW21, g_W21t); cudaGetSymbolAddress(&pW22, g_W22t);
    cudaGetSymbolAddress(&pW3, g_W3t);   cudaGetSymbolAddress(&pY, g_Y);
    __half *A0 = (__half*)pA0, *A1 = (__half*)pA1;
    __half *W1t = (__half*)pW1, *W2t = (__half*)pW2;
    __half *W21t = (__half*)pW21, *W22t = (__half*)pW22, *W3t = (__half*)pW3;
    float* Y = (float*)pY;

    cudaFuncSetAttribute(gemm_f16,
                         cudaFuncAttributeMaxDynamicSharedMemorySize, SMEMSZ);

    dim3 tb(32, 8);
    dim3 blk(256);
    dim3 gH(HID / 128, BATCH / 128);                     // (16, 64)
    dim3 gL((LOUT + 127) / 128, BATCH / 128);            // (17, 64)

    cast_f32_f16<<<(BATCH * DIN / 4 + 255) / 256, 256>>>(x, A0, BATCH * DIN / 4);
    wsplit_t_kernel<<<dim3(HID / 32, DIN / 32), tb>>>(W1, W1t, DIN, HID);
    wsplit_t_kernel<<<dim3(HID / 32, HID / 32), tb>>>(W2, W2t, HID, HID);
    wsplit_t_kernel<<<dim3(HID / 32, HID / 32), tb>>>(W21, W21t, HID, HID);
    wsplit_t_kernel<<<dim3(HID / 32, HID / 32), tb>>>(W22, W22t, HID, HID);
    wsplit_t_kernel<<<dim3(LOUT / 32, HID / 32), tb>>>(W3, W3t, HID, LOUT);

    gemm_f16<<<gH, blk, SMEMSZ>>>(A0, W1t, b1, A1, 0, DIN, HID, 1, 0);
    gemm_f16<<<gH, blk, SMEMSZ>>>(A1, W2t, b2, A0, 0, HID, HID, 1, 0);
    gemm_f16<<<gH, blk, SMEMSZ>>>(A0, W21t, b21, A1, 0, HID, HID, 1, 0);
    gemm_f16<<<gH, blk, SMEMSZ>>>(A1, W22t, b22, A0, 0, HID, HID, 1, 0);
    gemm_f16<<<gL, blk, SMEMSZ>>>(A0, W3t, b3, 0, Y, HID, LOUT, 0, 1);

    dim3 gsc(LOUT / 32, BATCH / 32);
    dim3 bsc(32, 8);
    scatter_tri<<<gsc, bsc>>>(Y, (float*)d_out);   // includes lower-tri zeros
}

// round 14
// speedup vs baseline: 3.9120x; 1.1377x over previous
#include <cuda_runtime.h>
#include <cuda_fp16.h>
#include <cstdint>

// ============================================================================
// ModelR: x[8192,1024] -> (Linear+LeakyReLU) x4 -> Linear -> tri-scatter
// Round 14: plain fp16 GEMM, BN 128->256 (warp tile 64x64) to restore MMA
// density (MMA:ldsm back to 4.0 = R8's saturated ratio). 2-stage cp.async,
// stage = A(128x144) + B(256x144) = 55296B, 110592B total.
// K-accumulation order unchanged vs R13 => rel_err expected bitwise 6.5488e-4.
// ============================================================================

#define BATCH 8192
#define DIN   1024
#define HID   2048
#define LOUT  2080
#define CPV   64

#define PITCH   144         // 128B payload (64 fp16) + 16B pad
#define OFF_A   0
#define OFF_B   18432       // 128 rows * 144B
#define STAGE   55296       // A tile + 256-row B tile
#define NSTAGE  2
#define SMEMSZ  (NSTAGE * STAGE)   // 110592 B

// ------------------------- device scratch (no allocs) -----------------------
__device__ __half g_A0[(size_t)BATCH * HID];
__device__ __half g_A1[(size_t)BATCH * HID];
__device__ __half g_W1t[(size_t)HID * DIN];
__device__ __half g_W2t[(size_t)HID * HID];
__device__ __half g_W21t[(size_t)HID * HID];
__device__ __half g_W22t[(size_t)HID * HID];
__device__ __half g_W3t[(size_t)LOUT * HID];
__device__ float  g_Y[(size_t)BATCH * LOUT];

// ------------------------------ PTX helpers ---------------------------------
__device__ __forceinline__ uint32_t smem_u32(const void* p) {
    uint32_t a;
    asm("{ .reg .u64 t; cvta.to.shared.u64 t, %1; cvt.u32.u64 %0, t; }"
        : "=r"(a) : "l"(p));
    return a;
}
__device__ __forceinline__ void cp16(uint32_t d, const void* s, int sz) {
    asm volatile("cp.async.cg.shared.global [%0], [%1], 16, %2;"
                 :: "r"(d), "l"(s), "r"(sz) : "memory");
}
__device__ __forceinline__ void cp_commit() {
    asm volatile("cp.async.commit_group;" ::: "memory");
}
template <int N> __device__ __forceinline__ void cp_wait() {
    asm volatile("cp.async.wait_group %0;" :: "n"(N) : "memory");
}
__device__ __forceinline__ void ldsm4(uint32_t* r, uint32_t a) {
    asm volatile("ldmatrix.sync.aligned.m8n8.x4.shared.b16 {%0,%1,%2,%3}, [%4];"
                 : "=r"(r[0]), "=r"(r[1]), "=r"(r[2]), "=r"(r[3]) : "r"(a));
}
__device__ __forceinline__ void mma16816(float* d, const uint32_t* a,
                                         const uint32_t* b) {
    asm volatile(
        "mma.sync.aligned.m16n8k16.row.col.f32.f16.f16.f32 "
        "{%0,%1,%2,%3}, {%4,%5,%6,%7}, {%8,%9}, {%0,%1,%2,%3};"
        : "+f"(d[0]), "+f"(d[1]), "+f"(d[2]), "+f"(d[3])
        : "r"(a[0]), "r"(a[1]), "r"(a[2]), "r"(a[3]), "r"(b[0]), "r"(b[1]));
}

// ------------------------------- GEMM kernel --------------------------------
// D[M, Ntot] = A[M,K] @ B[Ntot,K]^T + bias; optional lrelu.
// BM=128, BN=256, BK=64. 8 warps: warp tile 64x64 (warp_m 2 x warp_n 4).
__global__ void __launch_bounds__(256, 1)
gemm_f16(const __half* __restrict__ A, const __half* __restrict__ B,
         const float* __restrict__ bias,
         __half* __restrict__ Cout, float* __restrict__ Yout,
         int K, int Ntot, int act, int f32out)
{
    extern __shared__ char sm[];
    const uint32_t sbase = smem_u32(sm);

    const int tid  = threadIdx.x;
    const int wid  = tid >> 5;
    const int lane = tid & 31;
    const int warp_m = wid & 1;        // 2 x 64 rows
    const int warp_n = wid >> 1;       // 4 x 64 cols
    const int m0 = blockIdx.y * 128;
    const int n0 = blockIdx.x * 256;

    float acc[4][8][4];
#pragma unroll
    for (int i = 0; i < 4; i++)
#pragma unroll
        for (int j = 0; j < 8; j++)
#pragma unroll
            for (int k = 0; k < 4; k++) acc[i][j][k] = 0.f;

    const int kn = K >> 6;             // BK = 64

    // ldmatrix per-lane offsets (bytes, within a stage)
    const uint32_t a_off = (uint32_t)((warp_m * 64 + (lane & 15)) * PITCH
                                      + (lane >> 4) * 16);
    const uint32_t b_off = (uint32_t)((warp_n * 64 + (lane & 7) + ((lane >> 4) << 3)) * PITCH
                                      + ((lane >> 3) & 1) * 16);

    // cp.async: A tile 1024 chunks -> 4/thread; B tile 2048 chunks -> 8/thread.
#define LOAD_STAGE(KS, BUF)                                                          \
    {                                                                                \
        const int k0_ = (KS) << 6;                                                   \
        const uint32_t sb_ = sbase + (BUF) * STAGE;                                  \
        _Pragma("unroll")                                                            \
        for (int j_ = 0; j_ < 4; j_++) {                                             \
            int slot_ = tid + j_ * 256;                                              \
            int row_ = slot_ >> 3;                                                   \
            int col_ = slot_ & 7;                                                    \
            uint32_t d_ = sb_ + (uint32_t)(row_ * PITCH + col_ * 16);                \
            size_t ga_ = (size_t)(m0 + row_) * K + k0_ + col_ * 8;                   \
            cp16(d_ + OFF_A, A + ga_, 16);                                           \
        }                                                                            \
        _Pragma("unroll")                                                            \
        for (int j_ = 0; j_ < 8; j_++) {                                             \
            int slot_ = tid + j_ * 256;                                              \
            int row_ = slot_ >> 3;                                                   \
            int col_ = slot_ & 7;                                                    \
            uint32_t d_ = sb_ + (uint32_t)(row_ * PITCH + col_ * 16);                \
            int n_ = n0 + row_;                                                      \
            int sz_ = (n_ < Ntot) ? 16 : 0;                                          \
            int nc_ = (n_ < Ntot) ? n_ : (Ntot - 1);                                 \
            size_t gb_ = (size_t)nc_ * K + k0_ + col_ * 8;                           \
            cp16(d_ + OFF_B, B + gb_, sz_);                                          \
        }                                                                            \
    }

    LOAD_STAGE(0, 0); cp_commit();

    for (int ks = 0; ks < kn; ks++) {
        if (ks + 1 < kn) {
            LOAD_STAGE(ks + 1, (ks + 1) & 1); cp_commit(); cp_wait<1>();
        } else {
            cp_wait<0>();
        }
        __syncthreads();

        const uint32_t sb = sbase + (ks & 1) * STAGE;
#pragma unroll
        for (int kk = 0; kk < 4; kk++) {           // 4 x K16 per stage
            uint32_t ah[4][4];
#pragma unroll
            for (int mt = 0; mt < 4; mt++) {
                uint32_t o = a_off + (uint32_t)(mt * 16 * PITCH + kk * 32);
                ldsm4(ah[mt], sb + OFF_A + o);
            }
#pragma unroll
            for (int np = 0; np < 4; np++) {       // 4 x 16-col B panels
                uint32_t o = b_off + (uint32_t)(np * 16 * PITCH + kk * 32);
                uint32_t r[4];
                ldsm4(r, sb + OFF_B + o);
#pragma unroll
                for (int mt = 0; mt < 4; mt++) {
                    mma16816(acc[mt][2 * np],     ah[mt], r);
                    mma16816(acc[mt][2 * np + 1], ah[mt], r + 2);
                }
            }
        }
        if (ks + 1 < kn) __syncthreads();   // protect buf before next overwrite
    }

    // ---- epilogue: bias + act, write fp16 or fp32 ----
    const int mrow = lane >> 2;
    const int ncol = (lane & 3) * 2;
#pragma unroll
    for (int mt = 0; mt < 4; mt++) {
#pragma unroll
        for (int nt = 0; nt < 8; nt++) {
            int n = n0 + warp_n * 64 + nt * 8 + ncol;
            if (n >= Ntot) continue;
            float bs0 = __ldg(bias + n);
            float bs1 = __ldg(bias + n + 1);
#pragma unroll
            for (int half_ = 0; half_ < 2; half_++) {
                int m = m0 + warp_m * 64 + mt * 16 + mrow + half_ * 8;
                float v0 = acc[mt][nt][half_ * 2]     + bs0;
                float v1 = acc[mt][nt][half_ * 2 + 1] + bs1;
                if (act) {
                    v0 = v0 > 0.f ? v0 : 0.01f * v0;
                    v1 = v1 > 0.f ? v1 : 0.01f * v1;
                }
                if (f32out) {
                    *(float2*)(Yout + (size_t)m * Ntot + n) = make_float2(v0, v1);
                } else {
                    *(__half2*)(Cout + (size_t)m * Ntot + n) =
                        __halves2half2(__float2half_rn(v0), __float2half_rn(v1));
                }
            }
        }
    }
}

// --------------------------- cast / transpose -------------------------------
// x fp32 -> fp16 (float4-vectorized)
__global__ void cast_f32_f16(const float* __restrict__ in,
                             __half* __restrict__ out, int n4)
{
    int i = blockIdx.x * blockDim.x + threadIdx.x;
    if (i < n4) {
        float4 v = ((const float4*)in)[i];
        ((__half2*)out)[i * 2]     = __halves2half2(__float2half_rn(v.x), __float2half_rn(v.y));
        ((__half2*)out)[i * 2 + 1] = __halves2half2(__float2half_rn(v.z), __float2half_rn(v.w));
    }
}

// W[K,N] fp32 -> BT[N,K] fp16 (transpose). Dims %32 == 0.
__global__ void wsplit_t_kernel(const float* __restrict__ W,
                                __half* __restrict__ bt, int K, int N)
{
    __shared__ float t[32][33];
    const int n0 = blockIdx.x * 32, k0 = blockIdx.y * 32;
    const int tx = threadIdx.x, ty = threadIdx.y;
#pragma unroll
    for (int i = 0; i < 32; i += 8)
        t[ty + i][tx] = W[(size_t)(k0 + ty + i) * N + n0 + tx];
    __syncthreads();
#pragma unroll
    for (int i = 0; i < 32; i += 8) {
        float v = t[tx][ty + i];                 // element (k0+tx, n0+ty+i)
        bt[(size_t)(n0 + ty + i) * K + k0 + tx] = __float2half_rn(v);
    }
}

// ------------------------------- scatter ------------------------------------
// Writes upper-tri values AND mirrored lower-tri zeros (no separate memset).
__global__ void scatter_tri(const float* __restrict__ y, float* __restrict__ out)
{
    __shared__ float tile[32][33];
    const int l0 = blockIdx.x * 32;
    const int b0 = blockIdx.y * 32;
    const int txi = threadIdx.x;
    const int tyi = threadIdx.y;

#pragma unroll
    for (int i = 0; i < 32; i += 8)
        tile[tyi + i][txi] = y[(size_t)(b0 + tyi + i) * LOUT + l0 + txi];
    __syncthreads();

#pragma unroll
    for (int i = 0; i < 32; i += 8) {
        int l = l0 + tyi + i;
        float disc = 16641.0f - 8.0f * (float)l;
        int r = (int)((129.0f - sqrtf(disc)) * 0.5f);
        if (r < 0) r = 0;
        if (r > 63) r = 63;
        while (r < 63 && (r + 1) * (129 - (r + 1)) / 2 <= l) r++;
        while (r > 0 && r * (129 - r) / 2 > l) r--;
        int c = 63 - (l - r * (129 - r) / 2);
        float v = tile[txi][tyi + i];            // transposed read
        if (r == c && v <= 0.f) v = -v;
        out[((size_t)(r * CPV + c)) * BATCH + b0 + txi] = v;
        if (r != c)                              // mirrored zero (lower tri)
            out[((size_t)(c * CPV + r)) * BATCH + b0 + txi] = 0.f;
    }
}

// ------------------------------- launcher -----------------------------------
extern "C" void kernel_launch(void* const* d_in, const int* in_sizes, int n_in,
                              void* d_out, int out_size)
{
    // Identify inputs by element count (robust to metadata ordering).
    const float *x = 0, *W1 = 0, *W2 = 0, *W21 = 0, *W22 = 0, *W3 = 0;
    const float *b1 = 0, *b2 = 0, *b21 = 0, *b22 = 0, *b3 = 0;
    int nhh = 0, nbb = 0;
    for (int i = 0; i < n_in; i++) {
        const float* p = (const float*)d_in[i];
        switch (in_sizes[i]) {
            case 8388608: x  = p; break;
            case 2097152: W1 = p; break;
            case 4259840: W3 = p; break;
            case 2080:    b3 = p; break;
            case 4194304:
                if      (nhh == 0) W2  = p;
                else if (nhh == 1) W21 = p;
                else               W22 = p;
                nhh++; break;
            case 2048:
                if      (nbb == 0) b1  = p;
                else if (nbb == 1) b2  = p;
                else if (nbb == 2) b21 = p;
                else               b22 = p;
                nbb++; break;
            default: break;
        }
    }

    void *pA0, *pA1, *pW1, *pW2, *pW21, *pW22, *pW3, *pY;
    cudaGetSymbolAddress(&pA0, g_A0);    cudaGetSymbolAddress(&pA1, g_A1);
    cudaGetSymbolAddress(&pW1, g_W1t);   cudaGetSymbolAddress(&pW2, g_W2t);
    cudaGetSymbolAddress(&pW21, g_W21t); cudaGetSymbolAddress(&pW22, g_W22t);
    cudaGetSymbolAddress(&pW3, g_W3t);   cudaGetSymbolAddress(&pY, g_Y);
    __half *A0 = (__half*)pA0, *A1 = (__half*)pA1;
    __half *W1t = (__half*)pW1, *W2t = (__half*)pW2;
    __half *W21t = (__half*)pW21, *W22t = (__half*)pW22, *W3t = (__half*)pW3;
    float* Y = (float*)pY;

    cudaFuncSetAttribute(gemm_f16,
                         cudaFuncAttributeMaxDynamicSharedMemorySize, SMEMSZ);

    dim3 tb(32, 8);
    dim3 blk(256);
    dim3 gH(HID / 256, BATCH / 128);                     // (8, 64)
    dim3 gL((LOUT + 255) / 256, BATCH / 128);            // (9, 64)

    cast_f32_f16<<<(BATCH * DIN / 4 + 255) / 256, 256>>>(x, A0, BATCH * DIN / 4);
    wsplit_t_kernel<<<dim3(HID / 32, DIN / 32), tb>>>(W1, W1t, DIN, HID);
    wsplit_t_kernel<<<dim3(HID / 32, HID / 32), tb>>>(W2, W2t, HID, HID);
    wsplit_t_kernel<<<dim3(HID / 32, HID / 32), tb>>>(W21, W21t, HID, HID);
    wsplit_t_kernel<<<dim3(HID / 32, HID / 32), tb>>>(W22, W22t, HID, HID);
    wsplit_t_kernel<<<dim3(LOUT / 32, HID / 32), tb>>>(W3, W3t, HID, LOUT);

    gemm_f16<<<gH, blk, SMEMSZ>>>(A0, W1t, b1, A1, 0, DIN, HID, 1, 0);
    gemm_f16<<<gH, blk, SMEMSZ>>>(A1, W2t, b2, A0, 0, HID, HID, 1, 0);
    gemm_f16<<<gH, blk, SMEMSZ>>>(A0, W21t, b21, A1, 0, HID, HID, 1, 0);
    gemm_f16<<<gH, blk, SMEMSZ>>>(A1, W22t, b22, A0, 0, HID, HID, 1, 0);
    gemm_f16<<<gL, blk, SMEMSZ>>>(A0, W3t, b3, 0, Y, HID, LOUT, 0, 1);

    dim3 gsc(LOUT / 32, BATCH / 32);
    dim3 bsc(32, 8);
    scatter_tri<<<gsc, bsc>>>(Y, (float*)d_out);   // includes lower-tri zeros
}